// round 6
// baseline (speedup 1.0000x reference)
#include <cuda_runtime.h>
#include <cuda_bf16.h>
#include <math.h>

// Problem constants
static constexpr int S = 64;
static constexpr int B = 32;
static constexpr int H = 1024;
static constexpr int E = 512;
static constexpr int V = 32000;

// Scratch (static device memory; allocation-free per harness rules)
__device__ float g_x[S * B * E];      // embedded inputs  [S][B][E]   (4 MB)
__device__ float g_tops[S * B * H];   // layer-1 outputs  [S][B][H]   (8 MB)
__device__ float g_h0[2 * B * H];     // layer-0 hidden, double buffered
__device__ float g_h1init[B * H];     // initial layer-1 hidden

// ---------------------------------------------------------------------------
// Embedding gather: one block per (t,b) row, 128 threads x float4 = 512 floats
// ---------------------------------------------------------------------------
__global__ __launch_bounds__(128) void embed_kernel(
    const int* __restrict__ tok, const float* __restrict__ emb,
    float* __restrict__ x)
{
    int row = blockIdx.x;                  // t*B + b
    int t = tok[row];
    const float4* src = (const float4*)(emb + (size_t)t * E);
    float4* dst = (float4*)(x + (size_t)row * E);
    dst[threadIdx.x] = src[threadIdx.x];
}

// ---------------------------------------------------------------------------
// Copy initial hidden state into scratch buffers
// ---------------------------------------------------------------------------
__global__ __launch_bounds__(256) void init_kernel(const float* __restrict__ hidden)
{
    int i = blockIdx.x * blockDim.x + threadIdx.x;
    if (i < B * H)           g_h0[i] = hidden[i];
    else if (i < 2 * B * H)  g_h1init[i - B * H] = hidden[i];
}

// ---------------------------------------------------------------------------
// One RNN layer for one timestep:
//   hout[b][i] = tanh( sum_k in[b][k]*Wx[i][k] + sum_k hprev[b][k]*Wh[i][k] + bias[i] )
//
// grid = H/4 blocks, 8 warps/block. Warp w owns batches 4w..4w+3 and the
// block's 4 output columns. Lanes split K in float4 strides (coalesced),
// accumulate 4x4 products in registers, shfl_xor reduce.
// ---------------------------------------------------------------------------
__global__ __launch_bounds__(256) void rnn_layer_kernel(
    const float* __restrict__ in, int Kin,
    const float* __restrict__ hprev,
    const float* __restrict__ Wx,   // [H][Kin]
    const float* __restrict__ Wh,   // [H][H]
    const float* __restrict__ bias, // [H]
    float* __restrict__ hout)       // [B][H]
{
    const int warp = threadIdx.x >> 5;
    const int lane = threadIdx.x & 31;
    const int i0 = blockIdx.x * 4;
    const int b0 = warp * 4;

    float acc[4][4];
#pragma unroll
    for (int bb = 0; bb < 4; bb++)
#pragma unroll
        for (int j = 0; j < 4; j++) acc[bb][j] = 0.0f;

    // input contribution
    for (int kc = 0; kc < Kin; kc += 128) {
        int k = kc + lane * 4;
        float4 w[4];
#pragma unroll
        for (int j = 0; j < 4; j++)
            w[j] = *(const float4*)(Wx + (size_t)(i0 + j) * Kin + k);
#pragma unroll
        for (int bb = 0; bb < 4; bb++) {
            float4 xv = *(const float4*)(in + (size_t)(b0 + bb) * Kin + k);
#pragma unroll
            for (int j = 0; j < 4; j++) {
                acc[bb][j] += xv.x * w[j].x + xv.y * w[j].y
                            + xv.z * w[j].z + xv.w * w[j].w;
            }
        }
    }

    // recurrent contribution
    for (int kc = 0; kc < H; kc += 128) {
        int k = kc + lane * 4;
        float4 w[4];
#pragma unroll
        for (int j = 0; j < 4; j++)
            w[j] = *(const float4*)(Wh + (size_t)(i0 + j) * H + k);
#pragma unroll
        for (int bb = 0; bb < 4; bb++) {
            float4 hv = *(const float4*)(hprev + (size_t)(b0 + bb) * H + k);
#pragma unroll
            for (int j = 0; j < 4; j++) {
                acc[bb][j] += hv.x * w[j].x + hv.y * w[j].y
                            + hv.z * w[j].z + hv.w * w[j].w;
            }
        }
    }

    // warp reduction
#pragma unroll
    for (int bb = 0; bb < 4; bb++)
#pragma unroll
        for (int j = 0; j < 4; j++) {
#pragma unroll
            for (int off = 16; off > 0; off >>= 1)
                acc[bb][j] += __shfl_xor_sync(0xFFFFFFFFu, acc[bb][j], off);
        }

    if (lane == 0) {
#pragma unroll
        for (int bb = 0; bb < 4; bb++)
#pragma unroll
            for (int j = 0; j < 4; j++)
                hout[(size_t)(b0 + bb) * H + i0 + j] =
                    tanhf(acc[bb][j] + bias[i0 + j]);
    }
}

// ---------------------------------------------------------------------------
// Logits GEMM: C[m][n] = sum_k A[m][k] * W[n][k] + bias[n]
//   A = tops [2048][1024], W = Wout [32000][1024], C = logits [2048][32000]
// 128x128x16 SGEMM, 256 threads, 8x8 register micro-tiles,
// double-buffered smem with register-staged prefetch (1 barrier / K-step).
// Grid: x = M band (16, varies fastest) so concurrent CTAs share W tiles
// in L2; y = N band (250).
// ---------------------------------------------------------------------------
#define BM 128
#define BN 128
#define BK 16
__global__ __launch_bounds__(256) void logits_gemm_kernel(
    const float* __restrict__ A,
    const float* __restrict__ W,
    const float* __restrict__ bias,
    float* __restrict__ C)
{
    __shared__ float As[2][BK][BM + 4];
    __shared__ float Bs[2][BK][BN + 4];

    const int tid = threadIdx.x;
    const int bm = blockIdx.x * BM;   // M band varies fastest across bids
    const int bn = blockIdx.y * BN;   // N band
    const int lr = tid >> 2;       // 0..63
    const int lc = tid & 3;        // 0..3  (k-quad within BK)
    const int ty = tid >> 4;       // 0..15
    const int tx = tid & 15;       // 0..15
    const int K = H;

    float acc[8][8];
#pragma unroll
    for (int i = 0; i < 8; i++)
#pragma unroll
        for (int j = 0; j < 8; j++) acc[i][j] = 0.0f;

    // Preload tile 0 into buffer 0
#pragma unroll
    for (int r = 0; r < 2; r++) {
        int row = lr + r * 64;
        float4 va = *(const float4*)(A + (size_t)(bm + row) * K + lc * 4);
        As[0][lc * 4 + 0][row] = va.x;
        As[0][lc * 4 + 1][row] = va.y;
        As[0][lc * 4 + 2][row] = va.z;
        As[0][lc * 4 + 3][row] = va.w;
        float4 vb = *(const float4*)(W + (size_t)(bn + row) * K + lc * 4);
        Bs[0][lc * 4 + 0][row] = vb.x;
        Bs[0][lc * 4 + 1][row] = vb.y;
        Bs[0][lc * 4 + 2][row] = vb.z;
        Bs[0][lc * 4 + 3][row] = vb.w;
    }
    __syncthreads();

    int p = 0;
    for (int kc = 0; kc < K; kc += BK) {
        const bool has_next = (kc + BK) < K;
        float4 nva[2], nvb[2];
        if (has_next) {
#pragma unroll
            for (int r = 0; r < 2; r++) {
                int row = lr + r * 64;
                nva[r] = *(const float4*)(A + (size_t)(bm + row) * K + kc + BK + lc * 4);
                nvb[r] = *(const float4*)(W + (size_t)(bn + row) * K + kc + BK + lc * 4);
            }
        }

        // Compute on buffer p (overlaps with in-flight LDGs above)
#pragma unroll
        for (int k = 0; k < BK; k++) {
            float4 a0 = *(const float4*)&As[p][k][ty * 8];
            float4 a1 = *(const float4*)&As[p][k][ty * 8 + 4];
            float4 b0 = *(const float4*)&Bs[p][k][tx * 8];
            float4 b1 = *(const float4*)&Bs[p][k][tx * 8 + 4];
            float ar[8] = {a0.x, a0.y, a0.z, a0.w, a1.x, a1.y, a1.z, a1.w};
            float br[8] = {b0.x, b0.y, b0.z, b0.w, b1.x, b1.y, b1.z, b1.w};
#pragma unroll
            for (int i = 0; i < 8; i++)
#pragma unroll
                for (int j = 0; j < 8; j++)
                    acc[i][j] += ar[i] * br[j];
        }

        if (has_next) {
            int q = p ^ 1;
#pragma unroll
            for (int r = 0; r < 2; r++) {
                int row = lr + r * 64;
                As[q][lc * 4 + 0][row] = nva[r].x;
                As[q][lc * 4 + 1][row] = nva[r].y;
                As[q][lc * 4 + 2][row] = nva[r].z;
                As[q][lc * 4 + 3][row] = nva[r].w;
                Bs[q][lc * 4 + 0][row] = nvb[r].x;
                Bs[q][lc * 4 + 1][row] = nvb[r].y;
                Bs[q][lc * 4 + 2][row] = nvb[r].z;
                Bs[q][lc * 4 + 3][row] = nvb[r].w;
            }
            __syncthreads();
            p = q;
        }
    }

    // epilogue: add bias, vectorized stores
#pragma unroll
    for (int i = 0; i < 8; i++) {
        int m = bm + ty * 8 + i;
        int n = bn + tx * 8;
        float4 o0, o1;
        o0.x = acc[i][0] + bias[n + 0];
        o0.y = acc[i][1] + bias[n + 1];
        o0.z = acc[i][2] + bias[n + 2];
        o0.w = acc[i][3] + bias[n + 3];
        o1.x = acc[i][4] + bias[n + 4];
        o1.y = acc[i][5] + bias[n + 5];
        o1.z = acc[i][6] + bias[n + 6];
        o1.w = acc[i][7] + bias[n + 7];
        *(float4*)(C + (size_t)m * V + n)     = o0;
        *(float4*)(C + (size_t)m * V + n + 4) = o1;
    }
}

// ---------------------------------------------------------------------------
// Final hidden state -> output tail: [L][B][H] = [h0_final ; h1_final]
// ---------------------------------------------------------------------------
__global__ __launch_bounds__(256) void tail_kernel(float* __restrict__ out)
{
    int i = blockIdx.x * blockDim.x + threadIdx.x;
    if (i < B * H)            out[i] = g_h0[i];                      // final layer-0 hidden (even S ends at buf 0)
    else if (i < 2 * B * H)   out[i] = g_tops[(size_t)(S - 1) * B * H + (i - B * H)];
}

// ---------------------------------------------------------------------------
extern "C" void kernel_launch(void* const* d_in, const int* in_sizes, int n_in,
                              void* d_out, int out_size)
{
    const int*   tokens = (const int*)d_in[0];
    const float* hidden = (const float*)d_in[1];
    const float* emb    = (const float*)d_in[2];
    const float* Wx0    = (const float*)d_in[3];
    const float* Wh0    = (const float*)d_in[4];
    const float* bh0    = (const float*)d_in[5];
    const float* Wx1    = (const float*)d_in[6];
    const float* Wh1    = (const float*)d_in[7];
    const float* bh1    = (const float*)d_in[8];
    const float* Wout   = (const float*)d_in[9];
    const float* bout   = (const float*)d_in[10];
    float* out = (float*)d_out;

    float *px, *ptops, *ph0, *ph1i;
    cudaGetSymbolAddress((void**)&px,   g_x);
    cudaGetSymbolAddress((void**)&ptops, g_tops);
    cudaGetSymbolAddress((void**)&ph0,  g_h0);
    cudaGetSymbolAddress((void**)&ph1i, g_h1init);

    embed_kernel<<<S * B, 128>>>(tokens, emb, px);
    init_kernel<<<(2 * B * H + 255) / 256, 256>>>(hidden);

    for (int t = 0; t < S; t++) {
        const float* h0_prev = ph0 + (size_t)(t & 1) * B * H;
        float*       h0_new  = ph0 + (size_t)((t + 1) & 1) * B * H;
        rnn_layer_kernel<<<H / 4, 256>>>(px + (size_t)t * B * E, E,
                                         h0_prev, Wx0, Wh0, bh0, h0_new);
        const float* h1_prev = (t == 0) ? ph1i : (ptops + (size_t)(t - 1) * B * H);
        rnn_layer_kernel<<<H / 4, 256>>>(h0_new, H,
                                         h1_prev, Wx1, Wh1, bh1,
                                         ptops + (size_t)t * B * H);
    }

    logits_gemm_kernel<<<dim3((S * B) / BM, V / BN), 256>>>(ptops, Wout, bout, out);

    if (out_size >= S * B * V + 2 * B * H) {
        tail_kernel<<<(2 * B * H + 255) / 256, 256>>>(out + (size_t)S * B * V);
    }
}

// round 9
// speedup vs baseline: 2.1121x; 2.1121x over previous
#include <cuda_runtime.h>
#include <cuda_bf16.h>
#include <math.h>
#include <stdint.h>

// Problem constants
static constexpr int S = 64;
static constexpr int B = 32;
static constexpr int H = 1024;
static constexpr int E = 512;
static constexpr int V = 32000;

// Scratch (static device memory; allocation-free per harness rules)
__device__ float g_x[S * B * E];      // embedded inputs  [S][B][E]
__device__ float g_tops[S * B * H];   // layer-1 outputs  [S][B][H]
__device__ float g_h0[2 * B * H];     // layer-0 hidden, double buffered
__device__ float g_h1init[B * H];     // initial layer-1 hidden

// ---------------------------------------------------------------------------
// Embedding gather
// ---------------------------------------------------------------------------
__global__ __launch_bounds__(128) void embed_kernel(
    const int* __restrict__ tok, const float* __restrict__ emb,
    float* __restrict__ x)
{
    int row = blockIdx.x;                  // t*B + b
    int t = tok[row];
    const float4* src = (const float4*)(emb + (size_t)t * E);
    float4* dst = (float4*)(x + (size_t)row * E);
    dst[threadIdx.x] = src[threadIdx.x];
}

// ---------------------------------------------------------------------------
// Copy initial hidden state into scratch buffers
// ---------------------------------------------------------------------------
__global__ __launch_bounds__(256) void init_kernel(const float* __restrict__ hidden)
{
    int i = blockIdx.x * blockDim.x + threadIdx.x;
    if (i < B * H)           g_h0[i] = hidden[i];
    else if (i < 2 * B * H)  g_h1init[i - B * H] = hidden[i];
}

// ---------------------------------------------------------------------------
// RNN layer, v2 (unchanged from round 6): grid = H/8 = 128 blocks, 8 warps.
// Block owns 8 output columns; warp w owns batches 4w..4w+3.
// ---------------------------------------------------------------------------
template<int KIN>
__global__ __launch_bounds__(256) void rnn_layer_kernel2(
    const float* __restrict__ in,     // [B][KIN]
    const float* __restrict__ hprev,  // [B][H]
    const float* __restrict__ Wx,     // [H][KIN]
    const float* __restrict__ Wh,     // [H][H]
    const float* __restrict__ bias,   // [H]
    float* __restrict__ hout)         // [B][H]
{
    const int warp = threadIdx.x >> 5;
    const int lane = threadIdx.x & 31;
    const int i0 = blockIdx.x * 8;
    const int b0 = warp * 4;

    float acc[4][8];
#pragma unroll
    for (int bb = 0; bb < 4; bb++)
#pragma unroll
        for (int j = 0; j < 8; j++) acc[bb][j] = 0.0f;

    // input contribution
#pragma unroll 2
    for (int kc = 0; kc < KIN; kc += 128) {
        const int k = kc + lane * 4;
        float4 w[8];
#pragma unroll
        for (int j = 0; j < 8; j++)
            w[j] = *(const float4*)(Wx + (size_t)(i0 + j) * KIN + k);
#pragma unroll
        for (int bb = 0; bb < 4; bb++) {
            float4 xv = *(const float4*)(in + (size_t)(b0 + bb) * KIN + k);
#pragma unroll
            for (int j = 0; j < 8; j++) {
                acc[bb][j] += xv.x * w[j].x + xv.y * w[j].y
                            + xv.z * w[j].z + xv.w * w[j].w;
            }
        }
    }

    // recurrent contribution
#pragma unroll 2
    for (int kc = 0; kc < H; kc += 128) {
        const int k = kc + lane * 4;
        float4 w[8];
#pragma unroll
        for (int j = 0; j < 8; j++)
            w[j] = *(const float4*)(Wh + (size_t)(i0 + j) * H + k);
#pragma unroll
        for (int bb = 0; bb < 4; bb++) {
            float4 hv = *(const float4*)(hprev + (size_t)(b0 + bb) * H + k);
#pragma unroll
            for (int j = 0; j < 8; j++) {
                acc[bb][j] += hv.x * w[j].x + hv.y * w[j].y
                            + hv.z * w[j].z + hv.w * w[j].w;
            }
        }
    }

    // full butterfly reduce: every lane ends with the complete 32 sums
#pragma unroll
    for (int bb = 0; bb < 4; bb++)
#pragma unroll
        for (int j = 0; j < 8; j++) {
#pragma unroll
            for (int off = 16; off > 0; off >>= 1)
                acc[bb][j] += __shfl_xor_sync(0xFFFFFFFFu, acc[bb][j], off);
        }

    // lane l writes output element (bb = l>>3, j = l&7)
    {
        const int bb = lane >> 3;
        const int j  = lane & 7;
        hout[(size_t)(b0 + bb) * H + i0 + j] =
            tanhf(acc[bb][j] + bias[i0 + j]);
    }
}

// ---------------------------------------------------------------------------
// Logits GEMM on tensor cores (tf32 mma.sync.m16n8k8):
//   C[m][n] = sum_k A[m][k] * W[n][k] + bias[n]
//   A = tops [2048][1024] row-major (K contig) -> mma A row-major
//   W = Wout [32000][1024] row-major (K contig) -> mma B col-major (KxN)
// Block tile 128x128x32, 256 thr = 8 warps (2M x 4N), warp tile 64x32.
// Smem stride 36 floats -> all fragment LDS conflict-free (4g+t distinct).
// fp32 -> tf32 via cvt.rna at the global->smem stage (one cvt per element).
// Grid: x = M band (varies fastest) so concurrent CTAs share W tiles in L2.
// ---------------------------------------------------------------------------
#define GBM 128
#define GBN 128
#define GBK 32
#define GSTRIDE 36

__global__ __launch_bounds__(256) void logits_gemm_tf32(
    const float* __restrict__ A,
    const float* __restrict__ W,
    const float* __restrict__ bias,
    float* __restrict__ C)
{
    __shared__ uint32_t As[GBM][GSTRIDE];   // 128 x 36 x 4B = 18 KB
    __shared__ uint32_t Bs[GBN][GSTRIDE];   // 18 KB

    const int tid  = threadIdx.x;
    const int lane = tid & 31;
    const int warp = tid >> 5;
    const int wm   = warp >> 2;        // 0..1  (M)
    const int wn   = warp & 3;         // 0..3  (N)
    const int grp  = lane >> 2;        // 0..7
    const int tig  = lane & 3;         // 0..3

    const int bm = blockIdx.x * GBM;   // M band varies fastest
    const int bn = blockIdx.y * GBN;
    const int K  = H;

    // global->smem mapping: 4 float4 per thread per tile
    const int ldrow = tid >> 3;        // 0..31  (+32*r)
    const int ldcol = (tid & 7) * 4;   // 0,4,...,28

    float acc[4][4][4];                // [mt][nt][reg]
#pragma unroll
    for (int mt = 0; mt < 4; mt++)
#pragma unroll
        for (int nt = 0; nt < 4; nt++)
#pragma unroll
            for (int r = 0; r < 4; r++) acc[mt][nt][r] = 0.0f;

    // ---- preload chunk 0 ----
    {
        float4 na[4], nb[4];
#pragma unroll
        for (int r = 0; r < 4; r++) {
            na[r] = *(const float4*)(A + (size_t)(bm + ldrow + r * 32) * K + ldcol);
            nb[r] = *(const float4*)(W + (size_t)(bn + ldrow + r * 32) * K + ldcol);
        }
#pragma unroll
        for (int r = 0; r < 4; r++) {
            uint4 ua, ub;
            asm("cvt.rna.tf32.f32 %0, %1;" : "=r"(ua.x) : "f"(na[r].x));
            asm("cvt.rna.tf32.f32 %0, %1;" : "=r"(ua.y) : "f"(na[r].y));
            asm("cvt.rna.tf32.f32 %0, %1;" : "=r"(ua.z) : "f"(na[r].z));
            asm("cvt.rna.tf32.f32 %0, %1;" : "=r"(ua.w) : "f"(na[r].w));
            asm("cvt.rna.tf32.f32 %0, %1;" : "=r"(ub.x) : "f"(nb[r].x));
            asm("cvt.rna.tf32.f32 %0, %1;" : "=r"(ub.y) : "f"(nb[r].y));
            asm("cvt.rna.tf32.f32 %0, %1;" : "=r"(ub.z) : "f"(nb[r].z));
            asm("cvt.rna.tf32.f32 %0, %1;" : "=r"(ub.w) : "f"(nb[r].w));
            *(uint4*)&As[ldrow + r * 32][ldcol] = ua;
            *(uint4*)&Bs[ldrow + r * 32][ldcol] = ub;
        }
    }
    __syncthreads();

    for (int kc = 0; kc < K; kc += GBK) {
        const bool has_next = (kc + GBK) < K;
        float4 na[4], nb[4];
        if (has_next) {
#pragma unroll
            for (int r = 0; r < 4; r++) {
                na[r] = *(const float4*)(A + (size_t)(bm + ldrow + r * 32) * K + kc + GBK + ldcol);
                nb[r] = *(const float4*)(W + (size_t)(bn + ldrow + r * 32) * K + kc + GBK + ldcol);
            }
        }

        // compute: 4 k-slices of 8
#pragma unroll
        for (int ks = 0; ks < 4; ks++) {
            const int k0 = ks * 8;
            uint32_t af[4][4];
#pragma unroll
            for (int mt = 0; mt < 4; mt++) {
                const int gm = wm * 64 + mt * 16 + grp;
                af[mt][0] = As[gm][k0 + tig];
                af[mt][1] = As[gm + 8][k0 + tig];
                af[mt][2] = As[gm][k0 + tig + 4];
                af[mt][3] = As[gm + 8][k0 + tig + 4];
            }
            uint32_t bf[4][2];
#pragma unroll
            for (int nt = 0; nt < 4; nt++) {
                const int gn = wn * 32 + nt * 8 + grp;
                bf[nt][0] = Bs[gn][k0 + tig];
                bf[nt][1] = Bs[gn][k0 + tig + 4];
            }
#pragma unroll
            for (int mt = 0; mt < 4; mt++)
#pragma unroll
                for (int nt = 0; nt < 4; nt++) {
                    asm volatile(
                        "mma.sync.aligned.m16n8k8.row.col.f32.tf32.tf32.f32 "
                        "{%0,%1,%2,%3}, {%4,%5,%6,%7}, {%8,%9}, {%0,%1,%2,%3};\n"
                        : "+f"(acc[mt][nt][0]), "+f"(acc[mt][nt][1]),
                          "+f"(acc[mt][nt][2]), "+f"(acc[mt][nt][3])
                        : "r"(af[mt][0]), "r"(af[mt][1]),
                          "r"(af[mt][2]), "r"(af[mt][3]),
                          "r"(bf[nt][0]), "r"(bf[nt][1]));
                }
        }

        if (has_next) {
            __syncthreads();   // everyone done reading current tiles
#pragma unroll
            for (int r = 0; r < 4; r++) {
                uint4 ua, ub;
                asm("cvt.rna.tf32.f32 %0, %1;" : "=r"(ua.x) : "f"(na[r].x));
                asm("cvt.rna.tf32.f32 %0, %1;" : "=r"(ua.y) : "f"(na[r].y));
                asm("cvt.rna.tf32.f32 %0, %1;" : "=r"(ua.z) : "f"(na[r].z));
                asm("cvt.rna.tf32.f32 %0, %1;" : "=r"(ua.w) : "f"(na[r].w));
                asm("cvt.rna.tf32.f32 %0, %1;" : "=r"(ub.x) : "f"(nb[r].x));
                asm("cvt.rna.tf32.f32 %0, %1;" : "=r"(ub.y) : "f"(nb[r].y));
                asm("cvt.rna.tf32.f32 %0, %1;" : "=r"(ub.z) : "f"(nb[r].z));
                asm("cvt.rna.tf32.f32 %0, %1;" : "=r"(ub.w) : "f"(nb[r].w));
                *(uint4*)&As[ldrow + r * 32][ldcol] = ua;
                *(uint4*)&Bs[ldrow + r * 32][ldcol] = ub;
            }
            __syncthreads();
        }
    }

    // epilogue: bias add, float2 stores (c0,c1 / c2,c3 are adjacent cols)
#pragma unroll
    for (int mt = 0; mt < 4; mt++) {
#pragma unroll
        for (int nt = 0; nt < 4; nt++) {
            const int m0 = bm + wm * 64 + mt * 16 + grp;
            const int n0 = bn + wn * 32 + nt * 8 + 2 * tig;
            const float b0v = bias[n0], b1v = bias[n0 + 1];
            float2 lo = make_float2(acc[mt][nt][0] + b0v, acc[mt][nt][1] + b1v);
            float2 hi = make_float2(acc[mt][nt][2] + b0v, acc[mt][nt][3] + b1v);
            *(float2*)(C + (size_t)m0 * V + n0)       = lo;
            *(float2*)(C + (size_t)(m0 + 8) * V + n0) = hi;
        }
    }
}

// ---------------------------------------------------------------------------
// Final hidden state -> output tail: [L][B][H] = [h0_final ; h1_final]
// ---------------------------------------------------------------------------
__global__ __launch_bounds__(256) void tail_kernel(float* __restrict__ out)
{
    int i = blockIdx.x * blockDim.x + threadIdx.x;
    if (i < B * H)            out[i] = g_h0[i];                      // even S ends at buf 0
    else if (i < 2 * B * H)   out[i] = g_tops[(size_t)(S - 1) * B * H + (i - B * H)];
}

// ---------------------------------------------------------------------------
extern "C" void kernel_launch(void* const* d_in, const int* in_sizes, int n_in,
                              void* d_out, int out_size)
{
    const int*   tokens = (const int*)d_in[0];
    const float* hidden = (const float*)d_in[1];
    const float* emb    = (const float*)d_in[2];
    const float* Wx0    = (const float*)d_in[3];
    const float* Wh0    = (const float*)d_in[4];
    const float* bh0    = (const float*)d_in[5];
    const float* Wx1    = (const float*)d_in[6];
    const float* Wh1    = (const float*)d_in[7];
    const float* bh1    = (const float*)d_in[8];
    const float* Wout   = (const float*)d_in[9];
    const float* bout   = (const float*)d_in[10];
    float* out = (float*)d_out;

    float *px, *ptops, *ph0, *ph1i;
    cudaGetSymbolAddress((void**)&px,   g_x);
    cudaGetSymbolAddress((void**)&ptops, g_tops);
    cudaGetSymbolAddress((void**)&ph0,  g_h0);
    cudaGetSymbolAddress((void**)&ph1i, g_h1init);

    embed_kernel<<<S * B, 128>>>(tokens, emb, px);
    init_kernel<<<(2 * B * H + 255) / 256, 256>>>(hidden);

    for (int t = 0; t < S; t++) {
        const float* h0_prev = ph0 + (size_t)(t & 1) * B * H;
        float*       h0_new  = ph0 + (size_t)((t + 1) & 1) * B * H;
        rnn_layer_kernel2<E><<<H / 8, 256>>>(px + (size_t)t * B * E,
                                             h0_prev, Wx0, Wh0, bh0, h0_new);
        const float* h1_prev = (t == 0) ? ph1i : (ptops + (size_t)(t - 1) * B * H);
        rnn_layer_kernel2<H><<<H / 8, 256>>>(h0_new,
                                             h1_prev, Wx1, Wh1, bh1,
                                             ptops + (size_t)t * B * H);
    }

    logits_gemm_tf32<<<dim3((S * B) / GBM, V / GBN), 256>>>(ptops, Wout, bout, out);

    if (out_size >= S * B * V + 2 * B * H) {
        tail_kernel<<<(2 * B * H + 255) / 256, 256>>>(out + (size_t)S * B * V);
    }
}

// round 16
// speedup vs baseline: 2.1382x; 1.0124x over previous
#include <cuda_runtime.h>
#include <cuda_bf16.h>
#include <math.h>
#include <stdint.h>

// Problem constants
static constexpr int S = 64;
static constexpr int B = 32;
static constexpr int H = 1024;
static constexpr int E = 512;
static constexpr int V = 32000;

static constexpr int RNN_BLOCKS = 128;   // <= 148 SMs: all co-resident (1 CTA/SM)
static constexpr int SMEM_WFLOATS = 8 * E + 3 * 8 * H;     // 28672 floats
static constexpr int SMEM_WBYTES  = SMEM_WFLOATS * 4;      // 114688 B

// Scratch (static device memory; allocation-free per harness rules)
__device__ float g_x[S * B * E];      // embedded inputs  [S][B][E]
__device__ float g_tops[S * B * H];   // layer-1 outputs  [S][B][H]
__device__ float g_h0[2 * B * H];     // layer-0 hidden, double buffered
__device__ float g_h1init[B * H];     // initial layer-1 hidden

// Grid barrier state (returns to cnt=0 after every run; gen monotonic)
__device__ unsigned int g_bar_cnt = 0;
__device__ unsigned int g_bar_gen = 0;

__device__ __forceinline__ unsigned int ld_acq(unsigned int* p) {
    unsigned int v;
    asm volatile("ld.acquire.gpu.u32 %0, [%1];" : "=r"(v) : "l"(p) : "memory");
    return v;
}
__device__ __forceinline__ void st_rel(unsigned int* p, unsigned int v) {
    asm volatile("st.release.gpu.u32 [%0], %1;" :: "l"(p), "r"(v) : "memory");
}

__device__ __forceinline__ void grid_barrier() {
    __syncthreads();
    if (threadIdx.x == 0) {
        unsigned int* cnt = &g_bar_cnt;
        unsigned int* gen = &g_bar_gen;
        unsigned int my_gen = ld_acq(gen);
        __threadfence();                       // publish this block's stores
        if (atomicAdd(cnt, 1) == RNN_BLOCKS - 1) {
            *cnt = 0;                          // ordered before release below
            st_rel(gen, my_gen + 1);
        } else {
            while (ld_acq(gen) == my_gen) { }
        }
    }
    __syncthreads();
}

// ---------------------------------------------------------------------------
// Embedding gather
// ---------------------------------------------------------------------------
__global__ __launch_bounds__(128) void embed_kernel(
    const int* __restrict__ tok, const float* __restrict__ emb,
    float* __restrict__ x)
{
    int row = blockIdx.x;                  // t*B + b
    int t = tok[row];
    const float4* src = (const float4*)(emb + (size_t)t * E);
    float4* dst = (float4*)(x + (size_t)row * E);
    dst[threadIdx.x] = src[threadIdx.x];
}

// ---------------------------------------------------------------------------
// Copy initial hidden state into scratch buffers
// ---------------------------------------------------------------------------
__global__ __launch_bounds__(256) void init_kernel(const float* __restrict__ hidden)
{
    int i = blockIdx.x * blockDim.x + threadIdx.x;
    if (i < B * H)           g_h0[i] = hidden[i];
    else if (i < 2 * B * H)  g_h1init[i - B * H] = hidden[i];
}

// ---------------------------------------------------------------------------
// One layer-step with smem-resident weights.
// Warp w: batches 4w..4w+3; block cols i0..i0+7.
// ---------------------------------------------------------------------------
template<int KIN>
__device__ __forceinline__ void layer_step(
    const float* __restrict__ in,     // [B][KIN] gmem
    const float* __restrict__ hprev,  // [B][H] gmem
    const float* sWx,                 // [8][KIN] smem
    const float* sWh,                 // [8][H] smem
    float my_bias,                    // bias[i0 + (lane&7)]
    int i0, int warp, int lane,
    float* __restrict__ hout)         // [B][H] gmem
{
    const int b0 = warp * 4;

    float acc[4][8];
#pragma unroll
    for (int bb = 0; bb < 4; bb++)
#pragma unroll
        for (int j = 0; j < 8; j++) acc[bb][j] = 0.0f;

    // input contribution (weights from smem, activations from gmem/L2)
#pragma unroll 2
    for (int kc = 0; kc < KIN; kc += 128) {
        const int k = kc + lane * 4;
        float4 xv[4];
#pragma unroll
        for (int bb = 0; bb < 4; bb++)
            xv[bb] = *(const float4*)(in + (size_t)(b0 + bb) * KIN + k);
#pragma unroll
        for (int j = 0; j < 8; j++) {
            float4 w = *(const float4*)(sWx + j * KIN + k);
#pragma unroll
            for (int bb = 0; bb < 4; bb++) {
                acc[bb][j] += xv[bb].x * w.x + xv[bb].y * w.y
                            + xv[bb].z * w.z + xv[bb].w * w.w;
            }
        }
    }

    // recurrent contribution
#pragma unroll 2
    for (int kc = 0; kc < H; kc += 128) {
        const int k = kc + lane * 4;
        float4 hv[4];
#pragma unroll
        for (int bb = 0; bb < 4; bb++)
            hv[bb] = *(const float4*)(hprev + (size_t)(b0 + bb) * H + k);
#pragma unroll
        for (int j = 0; j < 8; j++) {
            float4 w = *(const float4*)(sWh + j * H + k);
#pragma unroll
            for (int bb = 0; bb < 4; bb++) {
                acc[bb][j] += hv[bb].x * w.x + hv[bb].y * w.y
                            + hv[bb].z * w.z + hv[bb].w * w.w;
            }
        }
    }

    // butterfly reduce: every lane ends with all 32 sums
#pragma unroll
    for (int bb = 0; bb < 4; bb++)
#pragma unroll
        for (int j = 0; j < 8; j++) {
#pragma unroll
            for (int off = 16; off > 0; off >>= 1)
                acc[bb][j] += __shfl_xor_sync(0xFFFFFFFFu, acc[bb][j], off);
        }

    const int bb = lane >> 3;
    const int j  = lane & 7;
    hout[(size_t)(b0 + bb) * H + i0 + j] = tanhf(acc[bb][j] + my_bias);
}

// ---------------------------------------------------------------------------
// Persistent recurrence kernel: all 64 timesteps, both layers.
// Block owns output columns i0..i0+7 of both layers; weights cached in smem.
// ---------------------------------------------------------------------------
__global__ __launch_bounds__(256, 1) void rnn_persistent_kernel(
    const float* __restrict__ x,      // [S][B][E]
    const float* __restrict__ Wx0, const float* __restrict__ Wh0,
    const float* __restrict__ bh0,
    const float* __restrict__ Wx1, const float* __restrict__ Wh1,
    const float* __restrict__ bh1,
    float* __restrict__ h0buf,        // [2][B][H]
    const float* __restrict__ h1init, // [B][H]
    float* __restrict__ tops)         // [S][B][H]
{
    extern __shared__ float smw[];
    float* sWx0 = smw;                    // 8*E
    float* sWh0 = sWx0 + 8 * E;           // 8*H
    float* sWx1 = sWh0 + 8 * H;           // 8*H
    float* sWh1 = sWx1 + 8 * H;           // 8*H

    const int tid  = threadIdx.x;
    const int warp = tid >> 5;
    const int lane = tid & 31;
    const int i0   = blockIdx.x * 8;

    // cooperative weight load (rows i0..i0+7 are contiguous in gmem)
    {
        const float4* s0 = (const float4*)(Wx0 + (size_t)i0 * E);
        float4* d0 = (float4*)sWx0;
        for (int i = tid; i < 8 * E / 4; i += 256) d0[i] = s0[i];
        const float4* s1 = (const float4*)(Wh0 + (size_t)i0 * H);
        float4* d1 = (float4*)sWh0;
        for (int i = tid; i < 8 * H / 4; i += 256) d1[i] = s1[i];
        const float4* s2 = (const float4*)(Wx1 + (size_t)i0 * H);
        float4* d2 = (float4*)sWx1;
        for (int i = tid; i < 8 * H / 4; i += 256) d2[i] = s2[i];
        const float4* s3 = (const float4*)(Wh1 + (size_t)i0 * H);
        float4* d3 = (float4*)sWh1;
        for (int i = tid; i < 8 * H / 4; i += 256) d3[i] = s3[i];
    }
    const float bias0 = bh0[i0 + (lane & 7)];
    const float bias1 = bh1[i0 + (lane & 7)];
    __syncthreads();

    for (int t = 0; t < S; t++) {
        const float* h0_prev = h0buf + (size_t)(t & 1) * B * H;
        float*       h0_new  = h0buf + (size_t)((t + 1) & 1) * B * H;

        layer_step<E>(x + (size_t)t * B * E, h0_prev, sWx0, sWh0,
                      bias0, i0, warp, lane, h0_new);
        grid_barrier();   // h0_new complete before layer 1 reads it

        const float* h1_prev = (t == 0) ? h1init : (tops + (size_t)(t - 1) * B * H);
        layer_step<H>(h0_new, h1_prev, sWx1, sWh1,
                      bias1, i0, warp, lane, tops + (size_t)t * B * H);
        grid_barrier();   // tops[t] complete before step t+1 reads it
    }
}

// ---------------------------------------------------------------------------
// Logits GEMM on tensor cores (tf32 mma.sync.m16n8k8) — unchanged.
// ---------------------------------------------------------------------------
#define GBM 128
#define GBN 128
#define GBK 32
#define GSTRIDE 36

__global__ __launch_bounds__(256) void logits_gemm_tf32(
    const float* __restrict__ A,
    const float* __restrict__ W,
    const float* __restrict__ bias,
    float* __restrict__ C)
{
    __shared__ uint32_t As[GBM][GSTRIDE];
    __shared__ uint32_t Bs[GBN][GSTRIDE];

    const int tid  = threadIdx.x;
    const int lane = tid & 31;
    const int warp = tid >> 5;
    const int wm   = warp >> 2;
    const int wn   = warp & 3;
    const int grp  = lane >> 2;
    const int tig  = lane & 3;

    const int bm = blockIdx.x * GBM;   // M band varies fastest
    const int bn = blockIdx.y * GBN;
    const int K  = H;

    const int ldrow = tid >> 3;
    const int ldcol = (tid & 7) * 4;

    float acc[4][4][4];
#pragma unroll
    for (int mt = 0; mt < 4; mt++)
#pragma unroll
        for (int nt = 0; nt < 4; nt++)
#pragma unroll
            for (int r = 0; r < 4; r++) acc[mt][nt][r] = 0.0f;

    {
        float4 na[4], nb[4];
#pragma unroll
        for (int r = 0; r < 4; r++) {
            na[r] = *(const float4*)(A + (size_t)(bm + ldrow + r * 32) * K + ldcol);
            nb[r] = *(const float4*)(W + (size_t)(bn + ldrow + r * 32) * K + ldcol);
        }
#pragma unroll
        for (int r = 0; r < 4; r++) {
            uint4 ua, ub;
            asm("cvt.rna.tf32.f32 %0, %1;" : "=r"(ua.x) : "f"(na[r].x));
            asm("cvt.rna.tf32.f32 %0, %1;" : "=r"(ua.y) : "f"(na[r].y));
            asm("cvt.rna.tf32.f32 %0, %1;" : "=r"(ua.z) : "f"(na[r].z));
            asm("cvt.rna.tf32.f32 %0, %1;" : "=r"(ua.w) : "f"(na[r].w));
            asm("cvt.rna.tf32.f32 %0, %1;" : "=r"(ub.x) : "f"(nb[r].x));
            asm("cvt.rna.tf32.f32 %0, %1;" : "=r"(ub.y) : "f"(nb[r].y));
            asm("cvt.rna.tf32.f32 %0, %1;" : "=r"(ub.z) : "f"(nb[r].z));
            asm("cvt.rna.tf32.f32 %0, %1;" : "=r"(ub.w) : "f"(nb[r].w));
            *(uint4*)&As[ldrow + r * 32][ldcol] = ua;
            *(uint4*)&Bs[ldrow + r * 32][ldcol] = ub;
        }
    }
    __syncthreads();

    for (int kc = 0; kc < K; kc += GBK) {
        const bool has_next = (kc + GBK) < K;
        float4 na[4], nb[4];
        if (has_next) {
#pragma unroll
            for (int r = 0; r < 4; r++) {
                na[r] = *(const float4*)(A + (size_t)(bm + ldrow + r * 32) * K + kc + GBK + ldcol);
                nb[r] = *(const float4*)(W + (size_t)(bn + ldrow + r * 32) * K + kc + GBK + ldcol);
            }
        }

#pragma unroll
        for (int ks = 0; ks < 4; ks++) {
            const int k0 = ks * 8;
            uint32_t af[4][4];
#pragma unroll
            for (int mt = 0; mt < 4; mt++) {
                const int gm = wm * 64 + mt * 16 + grp;
                af[mt][0] = As[gm][k0 + tig];
                af[mt][1] = As[gm + 8][k0 + tig];
                af[mt][2] = As[gm][k0 + tig + 4];
                af[mt][3] = As[gm + 8][k0 + tig + 4];
            }
            uint32_t bf[4][2];
#pragma unroll
            for (int nt = 0; nt < 4; nt++) {
                const int gn = wn * 32 + nt * 8 + grp;
                bf[nt][0] = Bs[gn][k0 + tig];
                bf[nt][1] = Bs[gn][k0 + tig + 4];
            }
#pragma unroll
            for (int mt = 0; mt < 4; mt++)
#pragma unroll
                for (int nt = 0; nt < 4; nt++) {
                    asm volatile(
                        "mma.sync.aligned.m16n8k8.row.col.f32.tf32.tf32.f32 "
                        "{%0,%1,%2,%3}, {%4,%5,%6,%7}, {%8,%9}, {%0,%1,%2,%3};\n"
                        : "+f"(acc[mt][nt][0]), "+f"(acc[mt][nt][1]),
                          "+f"(acc[mt][nt][2]), "+f"(acc[mt][nt][3])
                        : "r"(af[mt][0]), "r"(af[mt][1]),
                          "r"(af[mt][2]), "r"(af[mt][3]),
                          "r"(bf[nt][0]), "r"(bf[nt][1]));
                }
        }

        if (has_next) {
            __syncthreads();
#pragma unroll
            for (int r = 0; r < 4; r++) {
                uint4 ua, ub;
                asm("cvt.rna.tf32.f32 %0, %1;" : "=r"(ua.x) : "f"(na[r].x));
                asm("cvt.rna.tf32.f32 %0, %1;" : "=r"(ua.y) : "f"(na[r].y));
                asm("cvt.rna.tf32.f32 %0, %1;" : "=r"(ua.z) : "f"(na[r].z));
                asm("cvt.rna.tf32.f32 %0, %1;" : "=r"(ua.w) : "f"(na[r].w));
                asm("cvt.rna.tf32.f32 %0, %1;" : "=r"(ub.x) : "f"(nb[r].x));
                asm("cvt.rna.tf32.f32 %0, %1;" : "=r"(ub.y) : "f"(nb[r].y));
                asm("cvt.rna.tf32.f32 %0, %1;" : "=r"(ub.z) : "f"(nb[r].z));
                asm("cvt.rna.tf32.f32 %0, %1;" : "=r"(ub.w) : "f"(nb[r].w));
                *(uint4*)&As[ldrow + r * 32][ldcol] = ua;
                *(uint4*)&Bs[ldrow + r * 32][ldcol] = ub;
            }
            __syncthreads();
        }
    }

#pragma unroll
    for (int mt = 0; mt < 4; mt++) {
#pragma unroll
        for (int nt = 0; nt < 4; nt++) {
            const int m0 = bm + wm * 64 + mt * 16 + grp;
            const int n0 = bn + wn * 32 + nt * 8 + 2 * tig;
            const float b0v = bias[n0], b1v = bias[n0 + 1];
            float2 lo = make_float2(acc[mt][nt][0] + b0v, acc[mt][nt][1] + b1v);
            float2 hi = make_float2(acc[mt][nt][2] + b0v, acc[mt][nt][3] + b1v);
            *(float2*)(C + (size_t)m0 * V + n0)       = lo;
            *(float2*)(C + (size_t)(m0 + 8) * V + n0) = hi;
        }
    }
}

// ---------------------------------------------------------------------------
// Final hidden state -> output tail: [L][B][H] = [h0_final ; h1_final]
// ---------------------------------------------------------------------------
__global__ __launch_bounds__(256) void tail_kernel(float* __restrict__ out)
{
    int i = blockIdx.x * blockDim.x + threadIdx.x;
    if (i < B * H)            out[i] = g_h0[i];                      // even S ends at buf 0
    else if (i < 2 * B * H)   out[i] = g_tops[(size_t)(S - 1) * B * H + (i - B * H)];
}

// ---------------------------------------------------------------------------
extern "C" void kernel_launch(void* const* d_in, const int* in_sizes, int n_in,
                              void* d_out, int out_size)
{
    const int*   tokens = (const int*)d_in[0];
    const float* hidden = (const float*)d_in[1];
    const float* emb    = (const float*)d_in[2];
    const float* Wx0    = (const float*)d_in[3];
    const float* Wh0    = (const float*)d_in[4];
    const float* bh0    = (const float*)d_in[5];
    const float* Wx1    = (const float*)d_in[6];
    const float* Wh1    = (const float*)d_in[7];
    const float* bh1    = (const float*)d_in[8];
    const float* Wout   = (const float*)d_in[9];
    const float* bout   = (const float*)d_in[10];
    float* out = (float*)d_out;

    float *px, *ptops, *ph0, *ph1i;
    cudaGetSymbolAddress((void**)&px,   g_x);
    cudaGetSymbolAddress((void**)&ptops, g_tops);
    cudaGetSymbolAddress((void**)&ph0,  g_h0);
    cudaGetSymbolAddress((void**)&ph1i, g_h1init);

    // idempotent, stream-free, capture-legal; called every time (no static guard)
    cudaFuncSetAttribute(rnn_persistent_kernel,
                         cudaFuncAttributeMaxDynamicSharedMemorySize,
                         SMEM_WBYTES);

    embed_kernel<<<S * B, 128>>>(tokens, emb, px);
    init_kernel<<<(2 * B * H + 255) / 256, 256>>>(hidden);

    rnn_persistent_kernel<<<RNN_BLOCKS, 256, SMEM_WBYTES>>>(
        px, Wx0, Wh0, bh0, Wx1, Wh1, bh1, ph0, ph1i, ptops);

    logits_gemm_tf32<<<dim3((S * B) / GBM, V / GBN), 256>>>(ptops, Wout, bout, out);

    if (out_size >= S * B * V + 2 * B * H) {
        tail_kernel<<<(2 * B * H + 255) / 256, 256>>>(out + (size_t)S * B * V);
    }
}